// round 6
// baseline (speedup 1.0000x reference)
#include <cuda_runtime.h>
#include <cstdint>

// out[65536,64] = A[65536,512] @ B[512,64]; A[b,i*8+o] = prim_o(x[b,i]) on the fly,
// B = softmax(alphas)*coeffs built in-kernel. tf32 mma.sync m16n8k8, warp tile m64n64.

#define THREADS   256
#define PSTRIDE   36                    // stride 36 -> A-frag/STS banks conflict-free
#define SW_FLOATS 32768                 // B frags: [s=64][f=8][lane=32][2]
#define SP_FLOATS (512 * PSTRIDE)
#define SMEM_BYTES ((SW_FLOATS + SP_FLOATS) * 4)   // 204800 B

static __device__ __forceinline__ uint32_t f2tf32(float f) {
    uint32_t r;
    asm("cvt.rna.tf32.f32 %0, %1;" : "=r"(r) : "f"(f));
    return r;
}
static __device__ __forceinline__ float tf(float f) { return __uint_as_float(f2tf32(f)); }

static __device__ __forceinline__ void mma_tf32(float c[4], const uint32_t a[4],
                                                uint32_t b0, uint32_t b1) {
    asm volatile(
        "mma.sync.aligned.m16n8k8.row.col.f32.tf32.tf32.f32 "
        "{%0,%1,%2,%3}, {%4,%5,%6,%7}, {%8,%9}, {%0,%1,%2,%3};"
        : "+f"(c[0]), "+f"(c[1]), "+f"(c[2]), "+f"(c[3])
        : "r"(a[0]), "r"(a[1]), "r"(a[2]), "r"(a[3]), "r"(b0), "r"(b1));
}

// stage 4 features' primitives for one row: p points at sP + row*PSTRIDE
static __device__ __forceinline__ void stage_row(float* p, float4 xv) {
    float xs[4] = {xv.x, xv.y, xv.z, xv.w};
#pragma unroll
    for (int u = 0; u < 4; ++u) {
        float xx = xs[u];
        float x2 = xx * xx, x3 = x2 * xx;
        float ex = __expf(xx), lg = __logf(xx), sn = __sinf(xx);
        float rc;
        asm("rcp.approx.f32 %0, %1;" : "=f"(rc) : "f"(xx));
        *(float4*)(p + u * 8)     = make_float4(0.0f, tf(xx), tf(x2), tf(x3));
        *(float4*)(p + u * 8 + 4) = make_float4(tf(ex), tf(lg), tf(rc), tf(sn));
    }
}

__global__ void __launch_bounds__(THREADS, 1)
darts_kernel(const float* __restrict__ x, const float* __restrict__ alphas,
             const float* __restrict__ coeffs, float* __restrict__ out) {
    extern __shared__ float sm[];
    float* sW = sm;                 // 128 KB B fragments
    float* sP = sm + SW_FLOATS;     // 72 KB prim staging (4 features x 512 rows)

    int tid = threadIdx.x, lane = tid & 31, warp = tid >> 5;
    int qrow = lane >> 2, qcol = lane & 3;

    // ---- build W = softmax(alphas)*coeffs directly into mma B-fragment order
#pragma unroll
    for (int p = 0; p < 16; ++p) {
        int id = tid + p * 256;
        int i = id >> 6, j = id & 63;
        const float4* av = (const float4*)(alphas + (size_t)id * 8);
        const float4* cv = (const float4*)(coeffs + (size_t)id * 8);
        float4 a0 = av[0], a1 = av[1], c0 = cv[0], c1 = cv[1];
        float e0 = __expf(a0.x), e1 = __expf(a0.y), e2 = __expf(a0.z), e3 = __expf(a0.w);
        float e4 = __expf(a1.x), e5 = __expf(a1.y), e6 = __expf(a1.z), e7 = __expf(a1.w);
        float inv = 1.0f / (e0 + e1 + e2 + e3 + e4 + e5 + e6 + e7);
        float w[8] = {0.0f,          e1 * inv * c0.y, e2 * inv * c0.z, e3 * inv * c0.w,
                      e4 * inv * c1.x, e5 * inv * c1.y, e6 * inv * c1.z, e7 * inv * c1.w};
        int f = j >> 3;
#pragma unroll
        for (int k = 0; k < 8; ++k) {
            int ln = ((j & 7) << 2) | (k & 3);
            int slot = k >> 2;
            sW[((i * 8 + f) * 32 + ln) * 2 + slot] = tf(w[k]);
        }
    }
    __syncthreads();

    float acc[4][8][4];
#pragma unroll
    for (int mt = 0; mt < 4; ++mt)
#pragma unroll
        for (int f = 0; f < 8; ++f)
#pragma unroll
            for (int q = 0; q < 4; ++q) acc[mt][f][q] = 0.f;

    // lane l of warp w stages rows 64w+l and 64w+32+l (warp-self-contained)
    int rowA = warp * 64 + lane;
    size_t gRow = (size_t)blockIdx.x * 512 + rowA;
    const float4* x0 = (const float4*)(x + gRow * 64);
    const float4* x1 = (const float4*)(x + (gRow + 32) * 64);
    float* sp0 = sP + rowA * PSTRIDE;
    float* sp1 = sP + (rowA + 32) * PSTRIDE;

    for (int chunk = 0; chunk < 16; ++chunk) {
        float4 xa = x0[chunk];
        float4 xb = x1[chunk];
        stage_row(sp0, xa);
        stage_row(sp1, xb);
        __syncwarp();

#pragma unroll
        for (int s4 = 0; s4 < 4; ++s4) {
            int s = chunk * 4 + s4;
            uint32_t a[4][4];
            const float* base = sP + s4 * 8 + qcol;
#pragma unroll
            for (int mt = 0; mt < 4; ++mt) {
                int r0 = warp * 64 + mt * 16 + qrow;
                a[mt][0] = __float_as_uint(base[r0 * PSTRIDE]);
                a[mt][1] = __float_as_uint(base[(r0 + 8) * PSTRIDE]);
                a[mt][2] = __float_as_uint(base[r0 * PSTRIDE + 4]);
                a[mt][3] = __float_as_uint(base[(r0 + 8) * PSTRIDE + 4]);
            }
            const float2* wb = (const float2*)sW + s * 256 + lane;
#pragma unroll
            for (int f = 0; f < 8; ++f) {
                float2 b = wb[f * 32];
                uint32_t b0 = __float_as_uint(b.x);
                uint32_t b1 = __float_as_uint(b.y);
#pragma unroll
                for (int mt = 0; mt < 4; ++mt) mma_tf32(acc[mt][f], a[mt], b0, b1);
            }
        }
        __syncwarp();   // before next chunk overwrites sP
    }

    // ---- epilogue
#pragma unroll
    for (int mt = 0; mt < 4; ++mt) {
        size_t r = (size_t)blockIdx.x * 512 + warp * 64 + mt * 16 + qrow;
#pragma unroll
        for (int f = 0; f < 8; ++f) {
            int col = f * 8 + qcol * 2;
            *(float2*)(out + r * 64 + col) = make_float2(acc[mt][f][0], acc[mt][f][1]);
            *(float2*)(out + (r + 8) * 64 + col) = make_float2(acc[mt][f][2], acc[mt][f][3]);
        }
    }
}

extern "C" void kernel_launch(void* const* d_in, const int* in_sizes, int n_in,
                              void* d_out, int out_size) {
    const float* x      = (const float*)d_in[0];   // [65536, 64]
    const float* alphas = (const float*)d_in[1];   // [64, 64, 8]
    const float* coeffs = (const float*)d_in[2];   // [64, 64, 8]
    cudaFuncSetAttribute((const void*)darts_kernel,
                         cudaFuncAttributeMaxDynamicSharedMemorySize, SMEM_BYTES);
    darts_kernel<<<128, THREADS, SMEM_BYTES>>>(x, alphas, coeffs, (float*)d_out);
}

// round 8
// speedup vs baseline: 1.4448x; 1.4448x over previous
#include <cuda_runtime.h>
#include <cuda_fp16.h>
#include <cstdint>

// out[65536,64] = A[65536,512] @ B[512,64]; A[b,i*8+o] = prim_o(x[b,i]) on the fly,
// B = softmax(alphas)*coeffs built in-kernel, fp16 operands (same 10-bit mantissa
// as tf32 => same rel_err), fp32 accum. mma.sync m16n8k16, warp tile m32n64,
// 512 threads (16 warps), double-buffered prim staging, x prefetch.

#define THREADS    512
#define PST        20                       // u32 stride per staged row (banks: all-32 distinct)
#define SW_U32     16384                    // W frags: [s=32][f=8][lane=32][slot=2] fp16x2 = 64 KB
#define SP_U32     (512 * PST)              // one stage buffer: 40 KB
#define SMEM_BYTES ((SW_U32 + 2 * SP_U32) * 4)   // 147456 B

static __device__ __forceinline__ uint32_t pk(float lo, float hi) {
    __half2 h = __floats2half2_rn(lo, hi);   // x=lo (k even), y=hi (k odd)
    return *reinterpret_cast<uint32_t*>(&h);
}

static __device__ __forceinline__ void mma_fp16(float c[4], const uint32_t a[4],
                                                uint32_t b0, uint32_t b1) {
    asm volatile(
        "mma.sync.aligned.m16n8k16.row.col.f32.f16.f16.f32 "
        "{%0,%1,%2,%3}, {%4,%5,%6,%7}, {%8,%9}, {%0,%1,%2,%3};"
        : "+f"(c[0]), "+f"(c[1]), "+f"(c[2]), "+f"(c[3])
        : "r"(a[0]), "r"(a[1]), "r"(a[2]), "r"(a[3]), "r"(b0), "r"(b1));
}

__global__ void __launch_bounds__(THREADS, 1)
darts_kernel(const float* __restrict__ x, const float* __restrict__ alphas,
             const float* __restrict__ coeffs, float* __restrict__ out) {
    extern __shared__ uint32_t sm[];
    uint32_t* sW = sm;                // 64 KB B fragments (fp16x2)
    uint32_t* sP = sm + SW_U32;       // 2 x 40 KB prim staging

    int tid = threadIdx.x, lane = tid & 31, warp = tid >> 5;
    int qrow = lane >> 2, qcol = lane & 3;

    // ---- build W = softmax(alphas)*coeffs into fp16 B-fragment order
    // B[k=i*8+op][n=j]; kstep s=i>>1, slot=i&1, pair qcol <-> ops 2q,2q+1
#pragma unroll
    for (int p = 0; p < 8; ++p) {
        int id = tid + p * 512;
        int i = id >> 6, j = id & 63;
        const float4* av = (const float4*)(alphas + (size_t)id * 8);
        const float4* cv = (const float4*)(coeffs + (size_t)id * 8);
        float4 a0 = av[0], a1 = av[1], c0 = cv[0], c1 = cv[1];
        float e0 = __expf(a0.x), e1 = __expf(a0.y), e2 = __expf(a0.z), e3 = __expf(a0.w);
        float e4 = __expf(a1.x), e5 = __expf(a1.y), e6 = __expf(a1.z), e7 = __expf(a1.w);
        float inv = 1.0f / (e0 + e1 + e2 + e3 + e4 + e5 + e6 + e7);
        float w[8] = {0.0f,            e1 * inv * c0.y, e2 * inv * c0.z, e3 * inv * c0.w,
                      e4 * inv * c1.x, e5 * inv * c1.y, e6 * inv * c1.z, e7 * inv * c1.w};
        int s = i >> 1, slot = i & 1, fb = j >> 3;
        uint32_t base = (uint32_t)(((s * 8 + fb) * 32 + (j & 7) * 4) * 2 + slot);
#pragma unroll
        for (int q = 0; q < 4; ++q)
            sW[base + q * 2] = pk(w[2 * q], w[2 * q + 1]);
    }
    __syncthreads();

    float acc[2][8][4];
#pragma unroll
    for (int mt = 0; mt < 2; ++mt)
#pragma unroll
        for (int f = 0; f < 8; ++f)
#pragma unroll
            for (int q = 0; q < 4; ++q) acc[mt][f][q] = 0.f;

    // thread stages row warp*32+lane (warp-self-contained -> __syncwarp only)
    int rowA = warp * 32 + lane;
    const float4* xp = (const float4*)(x + ((size_t)blockIdx.x * 512 + rowA) * 64);

    float4 xv = xp[0];
    for (int chunk = 0; chunk < 16; ++chunk) {
        uint32_t* spb = sP + (chunk & 1) * SP_U32;
        float4 xn = xv;
        if (chunk < 15) xn = xp[chunk + 1];          // prefetch next chunk

        // ---- stage 4 features (8 ops each) as fp16x2 pairs: [row][u][q]
        float xs[4] = {xv.x, xv.y, xv.z, xv.w};
#pragma unroll
        for (int u = 0; u < 4; ++u) {
            float xx = xs[u];
            float x2 = xx * xx, x3 = x2 * xx;
            float ex = __expf(xx), lg = __logf(xx), sn = __sinf(xx);
            float rc;
            asm("rcp.approx.f32 %0, %1;" : "=f"(rc) : "f"(xx));
            uint4 v;
            v.x = pk(0.0f, xx);   // ops 0,1
            v.y = pk(x2, x3);     // ops 2,3
            v.z = pk(ex, lg);     // ops 4,5
            v.w = pk(rc, sn);     // ops 6,7
            *(uint4*)(spb + rowA * PST + u * 4) = v;
        }
        __syncwarp();

        // ---- 2 k16-steps (features 2kk, 2kk+1 of this chunk)
#pragma unroll
        for (int kk = 0; kk < 2; ++kk) {
            int s = chunk * 2 + kk;
            uint32_t a[2][4];
#pragma unroll
            for (int mt = 0; mt < 2; ++mt) {
                int r0 = warp * 32 + mt * 16 + qrow;
                const uint32_t* p0 = spb + (2 * kk) * 4 + qcol;        // feature even (k-low)
                const uint32_t* p1 = spb + (2 * kk + 1) * 4 + qcol;    // feature odd  (k-high)
                a[mt][0] = p0[r0 * PST];
                a[mt][1] = p0[(r0 + 8) * PST];
                a[mt][2] = p1[r0 * PST];
                a[mt][3] = p1[(r0 + 8) * PST];
            }
            const uint2* wb = (const uint2*)sW + (s * 8) * 32 + lane;
#pragma unroll
            for (int f = 0; f < 8; ++f) {
                uint2 b = wb[f * 32];
                mma_fp16(acc[0][f], a[0], b.x, b.y);
                mma_fp16(acc[1][f], a[1], b.x, b.y);
            }
        }
        xv = xn;   // double-buffered staging: no trailing syncwarp needed
    }

    // ---- epilogue: c0,c1 -> (row, 2qcol..+1), c2,c3 -> (row+8, ...)
#pragma unroll
    for (int mt = 0; mt < 2; ++mt) {
        size_t r = (size_t)blockIdx.x * 512 + warp * 32 + mt * 16 + qrow;
#pragma unroll
        for (int f = 0; f < 8; ++f) {
            int col = f * 8 + qcol * 2;
            *(float2*)(out + r * 64 + col)       = make_float2(acc[mt][f][0], acc[mt][f][1]);
            *(float2*)(out + (r + 8) * 64 + col) = make_float2(acc[mt][f][2], acc[mt][f][3]);
        }
    }
}

extern "C" void kernel_launch(void* const* d_in, const int* in_sizes, int n_in,
                              void* d_out, int out_size) {
    const float* x      = (const float*)d_in[0];   // [65536, 64]
    const float* alphas = (const float*)d_in[1];   // [64, 64, 8]
    const float* coeffs = (const float*)d_in[2];   // [64, 64, 8]
    cudaFuncSetAttribute((const void*)darts_kernel,
                         cudaFuncAttributeMaxDynamicSharedMemorySize, SMEM_BYTES);
    darts_kernel<<<128, THREADS, SMEM_BYTES>>>(x, alphas, coeffs, (float*)d_out);
}